// round 9
// baseline (speedup 1.0000x reference)
#include <cuda_runtime.h>
#include <cstdint>

// CSPN propagation:
//   out[b,0,y,x] = sum_{t=0..24} gw[b,t,y+2,x+2] * src_t(y+2-t/5, x+2-t%5)
// src_t = h0 for t==12 (center) else hn; zero outside [0,H)x[0,W).
// gw (4,25,356,1220) f32, hn/h0 (4,1,352,1216) f32, out (4,1,352,1216) f32.
//
// Interior threads take x = 4q+2 so the weight offset (y+2)*1220+(x+2) is
// 16B-aligned -> one LDG.128 per tap (25 total) and the hn span [x-2,x+5]
// is two aligned LDG.128. One thread per row handles the 4 edge pixels.

#define K 5
#define Hc 352
#define Wc 1216
#define Hp 356
#define Wp 1220
#define Bc 4
#define QPR 304                      // q-slots per row: 303 interior + 1 edge

__global__ __launch_bounds__(256)
void cspn_kernel(const float* __restrict__ gw,
                 const float* __restrict__ hn,
                 const float* __restrict__ h0,
                 float* __restrict__ out)
{
    int idx = blockIdx.x * blockDim.x + threadIdx.x;
    const int total = Bc * Hc * QPR;                 // 428032
    if (idx >= total) return;

    const int q   = idx % QPR;
    int rem       = idx / QPR;
    const int y   = rem % Hc;
    const int b   = rem / Hc;

    const size_t PLANE = (size_t)Hp * Wp;            // 434320
    const float* wrow = gw + (size_t)b * 25 * PLANE + (size_t)(y + 2) * Wp;
    const float* hb   = hn + (size_t)b * Hc * Wc;
    const float* h0b  = h0 + (size_t)b * Hc * Wc;
    float* ob         = out + (size_t)b * Hc * Wc + (size_t)y * Wc;

    if (q < QPR - 1) {
        // ---------------- interior: 4 pixels at x = 4q+2 ----------------
        const int x = 4 * q + 2;
        const float* wb = wrow + (x + 2);            // offset % 4 == 0

        float acc0 = 0.f, acc1 = 0.f, acc2 = 0.f, acc3 = 0.f;

        // center-tap h0 at [x, x+3]: offset % 4 == 2 -> two aligned float2
        const float2 cA = *reinterpret_cast<const float2*>(h0b + (size_t)y * Wc + x);
        const float2 cB = *reinterpret_cast<const float2*>(h0b + (size_t)y * Wc + x + 2);

        #pragma unroll
        for (int dy = 0; dy < K; ++dy) {
            // batch the 5 weight LDG.128 for this tap row
            float4 w[5];
            #pragma unroll
            for (int c = 0; c < 5; ++c)
                w[c] = __ldg(reinterpret_cast<const float4*>(wb + (size_t)(dy * 5 + c) * PLANE));

            // hn span [x-2, x+5]: two aligned float4 (x-2 % 4 == 0), y-predicated
            const int iy = y + 2 - dy;
            const bool yok = (unsigned)iy < (unsigned)Hc;
            float4 va = make_float4(0.f, 0.f, 0.f, 0.f);
            float4 vb = make_float4(0.f, 0.f, 0.f, 0.f);
            if (yok) {
                const float* rp = hb + (size_t)iy * Wc;
                va = __ldg(reinterpret_cast<const float4*>(rp + x - 2));
                vb = __ldg(reinterpret_cast<const float4*>(rp + x + 2));
            }
            float v[8] = { va.x, va.y, va.z, va.w, vb.x, vb.y, vb.z, vb.w };

            #pragma unroll
            for (int c = 0; c < 5; ++c) {
                float s0, s1, s2, s3;
                if (dy == 2 && c == 2) {             // center tap t=12 -> h0
                    s0 = cA.x; s1 = cA.y; s2 = cB.x; s3 = cB.y;
                } else {
                    const int base = 4 - c;
                    s0 = v[base + 0]; s1 = v[base + 1];
                    s2 = v[base + 2]; s3 = v[base + 3];
                }
                acc0 = fmaf(w[c].x, s0, acc0);
                acc1 = fmaf(w[c].y, s1, acc1);
                acc2 = fmaf(w[c].z, s2, acc2);
                acc3 = fmaf(w[c].w, s3, acc3);
            }
        }

        // store: offset % 4 == 2 -> two aligned float2
        float2 oA; oA.x = acc0; oA.y = acc1;
        float2 oB; oB.x = acc2; oB.y = acc3;
        *reinterpret_cast<float2*>(ob + x)     = oA;
        *reinterpret_cast<float2*>(ob + x + 2) = oB;
    } else {
        // ---------------- edge: pixels x in {0, 1, 1214, 1215} ----------------
        const int xs[4] = { 0, 1, Wc - 2, Wc - 1 };
        #pragma unroll
        for (int p = 0; p < 4; ++p) {
            const int x = xs[p];
            float acc = 0.f;
            #pragma unroll
            for (int t = 0; t < 25; ++t) {
                const int dy = t / K;
                const int dx = t % K;
                const float wv = __ldg(wrow + (size_t)t * PLANE + (x + 2));
                float sv;
                if (t == 12) {
                    sv = __ldg(h0b + (size_t)y * Wc + x);
                } else {
                    const int iy = y + 2 - dy;
                    const int ix = x + 2 - dx;
                    sv = ((unsigned)iy < (unsigned)Hc && (unsigned)ix < (unsigned)Wc)
                           ? __ldg(hb + (size_t)iy * Wc + ix) : 0.f;
                }
                acc = fmaf(wv, sv, acc);
            }
            ob[x] = acc;
        }
    }
}

extern "C" void kernel_launch(void* const* d_in, const int* in_sizes, int n_in,
                              void* d_out, int out_size)
{
    const float* gw = (const float*)d_in[0];
    const float* hn = (const float*)d_in[1];
    const float* h0 = (const float*)d_in[2];
    float* out = (float*)d_out;

    const int total = Bc * Hc * QPR;                 // 428032 threads
    const int threads = 256;
    const int blocks = (total + threads - 1) / threads;
    cspn_kernel<<<blocks, threads>>>(gw, hn, h0, out);
}